// round 3
// baseline (speedup 1.0000x reference)
#include <cuda_runtime.h>
#include <cuda_bf16.h>

// ---------------------------------------------------------------------------
// B=128, T=32, N=196, E=FD=H=A=1024, 4H=4096, E+FD=2048
// Inputs: 0 feats[128,196,1024] 1 embeddings[128,32,1024] 2 Wf 3 Wh 4 b_att
//         5 v 6 W_ih0[4096,2048] 7 W_hh0[4096,1024] 8 b_ih0 9 b_hh0
//         10 W_ih1 11 W_hh1 12 b_ih1 13 b_hh1
// Output: [128,32,1024] fp32
// ---------------------------------------------------------------------------

#define ULL unsigned long long

// ------------------------------ scratch ------------------------------------
__device__ __nv_bfloat16 g_fprojb[25088 * 1024];   // [b][n][a] bf16   51.4 MB
__device__ __nv_bfloat16 g_featsb[25088 * 1024];   // feats bf16       51.4 MB
__device__ float g_pre0[32 * 128 * 4096];          // [t][b][j]        67.1 MB
__device__ float g_w1c[4096 * 1024];               // W_ih1+W_hh1      16.8 MB
__device__ float g_b0c[4096];
__device__ float g_b1c[4096];
__device__ float g_h0[128 * 1024];
__device__ float g_c0[128 * 1024];
__device__ float g_q[128 * 1024];
__device__ float g_scores[128 * 196];
__device__ float g_attn[128 * 1024];
__device__ float g_gates[128 * 4096];
__device__ float g_h0all[32 * 128 * 1024];         // [t][b][h]
__device__ float g_c0all[32 * 128 * 1024];
__device__ float g_gates1[32 * 128 * 4096];        // 67.1 MB

// ------------------------------ helpers ------------------------------------
__device__ __forceinline__ ULL pack2(float x, float y) {
    ULL r; asm("mov.b64 %0, {%1, %2};" : "=l"(r) : "f"(x), "f"(y)); return r;
}
__device__ __forceinline__ float2 unpack2(ULL v) {
    float2 r; asm("mov.b64 {%0, %1}, %2;" : "=f"(r.x), "=f"(r.y) : "l"(v)); return r;
}
__device__ __forceinline__ void fma2(ULL& d, ULL a, ULL b) {
    asm("fma.rn.f32x2 %0, %1, %2, %0;" : "+l"(d) : "l"(a), "l"(b));
}
__device__ __forceinline__ float fast_tanh(float x) {
    float r; asm("tanh.approx.f32 %0, %1;" : "=f"(r) : "f"(x)); return r;
}
__device__ __forceinline__ float sigf(float x) { return 1.f / (1.f + __expf(-x)); }

// ---------------------------------------------------------------------------
// Generic tiled GEMM:  C[M,N] = A[M,K] * op(B) (+bias)
//   BT: B is [N,K] (C = A*B^T); else B is [K,N]
//   PERM: A row m reads source row (m%128)*32 + m/128   (for pre0)
//   OUTBF: store C as bf16
// 128x128x8 tiles, 256 threads, 8x8/thread, f32x2.
// ---------------------------------------------------------------------------
template <bool BT, bool PERM, bool BIAS, bool OUTBF>
__global__ __launch_bounds__(256) void gemm128_kernel(
    const float* __restrict__ A, int lda,
    const float* __restrict__ B, int ldb,
    void* __restrict__ Cv, int ldc,
    const float* __restrict__ bias, int K)
{
    __shared__ __align__(16) float As[8][128];
    __shared__ __align__(16) float Bs[8][128];

    const int tid = threadIdx.x;
    const int m0 = blockIdx.x * 128;
    const int n0 = blockIdx.y * 128;

    const int tx = tid & 15;
    const int ty = tid >> 4;

    ULL acc[8][4];
#pragma unroll
    for (int i = 0; i < 8; i++)
#pragma unroll
        for (int j = 0; j < 4; j++) acc[i][j] = 0ull;

    const int arow = tid >> 1, akq = tid & 1;
    int ar = m0 + arow;
    if (PERM) ar = (ar & 127) * 32 + (ar >> 7);
    const float* Aptr = A + (long)ar * lda + akq * 4;

    const float* Bptr;
    if (BT) {
        Bptr = B + (long)(n0 + (tid >> 1)) * ldb + (tid & 1) * 4;
    } else {
        Bptr = B + (long)(tid >> 5) * ldb + n0 + (tid & 31) * 4;
    }

    for (int kt = 0; kt < K; kt += 8) {
        float4 a4 = *(const float4*)(Aptr + kt);
        As[akq * 4 + 0][arow] = a4.x;
        As[akq * 4 + 1][arow] = a4.y;
        As[akq * 4 + 2][arow] = a4.z;
        As[akq * 4 + 3][arow] = a4.w;
        if (BT) {
            float4 b4 = *(const float4*)(Bptr + kt);
            const int brow = tid >> 1, bkq = tid & 1;
            Bs[bkq * 4 + 0][brow] = b4.x;
            Bs[bkq * 4 + 1][brow] = b4.y;
            Bs[bkq * 4 + 2][brow] = b4.z;
            Bs[bkq * 4 + 3][brow] = b4.w;
        } else {
            float4 b4 = *(const float4*)(Bptr + (long)kt * ldb);
            *(float4*)&Bs[tid >> 5][(tid & 31) * 4] = b4;
        }
        __syncthreads();
#pragma unroll
        for (int kk = 0; kk < 8; kk++) {
            float4 aA = *(const float4*)&As[kk][ty * 8];
            float4 aB = *(const float4*)&As[kk][ty * 8 + 4];
            ulonglong2 b0 = *(const ulonglong2*)&Bs[kk][tx * 8];
            ulonglong2 b1 = *(const ulonglong2*)&Bs[kk][tx * 8 + 4];
            ULL ap[8];
            ap[0] = pack2(aA.x, aA.x); ap[1] = pack2(aA.y, aA.y);
            ap[2] = pack2(aA.z, aA.z); ap[3] = pack2(aA.w, aA.w);
            ap[4] = pack2(aB.x, aB.x); ap[5] = pack2(aB.y, aB.y);
            ap[6] = pack2(aB.z, aB.z); ap[7] = pack2(aB.w, aB.w);
#pragma unroll
            for (int i = 0; i < 8; i++) {
                fma2(acc[i][0], ap[i], b0.x);
                fma2(acc[i][1], ap[i], b0.y);
                fma2(acc[i][2], ap[i], b1.x);
                fma2(acc[i][3], ap[i], b1.y);
            }
        }
        __syncthreads();
    }

#pragma unroll
    for (int i = 0; i < 8; i++) {
        const long row = m0 + ty * 8 + i;
#pragma unroll
        for (int j = 0; j < 4; j++) {
            float2 vv = unpack2(acc[i][j]);
            const int col = n0 + tx * 8 + j * 2;
            if (BIAS) { vv.x += bias[col]; vv.y += bias[col + 1]; }
            if (OUTBF) {
                __nv_bfloat16* Cb = (__nv_bfloat16*)Cv;
                *(__nv_bfloat162*)&Cb[row * ldc + col] = __float22bfloat162_rn(vv);
            } else {
                float* Cf = (float*)Cv;
                Cf[row * ldc + col] = vv.x;
                Cf[row * ldc + col + 1] = vv.y;
            }
        }
    }
}

// ---------------------------------------------------------------------------
// q = h0 @ Wh   [128,1024]x[1024,1024], full-K per block, BN=8, grid 128
// ---------------------------------------------------------------------------
__global__ __launch_bounds__(256) void qgemm_kernel(const float* __restrict__ Wh)
{
    __shared__ __align__(16) float As[16][128];
    __shared__ __align__(16) float Bs[16][8];

    const int tid = threadIdx.x;
    const int n0 = blockIdx.x * 8;
    const int ty = tid >> 3;   // rows ty*4..ty*4+3
    const int tx = tid & 7;    // col tx

    ULL acc01 = 0ull, acc23 = 0ull;

    for (int kt = 0; kt < 1024; kt += 16) {
#pragma unroll
        for (int u = 0; u < 2; u++) {
            int s = tid * 2 + u;
            int row = s >> 2, kc = s & 3;
            float4 a4 = *(const float4*)(g_h0 + row * 1024 + kt + kc * 4);
            As[kc * 4 + 0][row] = a4.x;
            As[kc * 4 + 1][row] = a4.y;
            As[kc * 4 + 2][row] = a4.z;
            As[kc * 4 + 3][row] = a4.w;
        }
        if (tid < 32) {
            int k = tid >> 1, hf = tid & 1;
            float4 b4 = *(const float4*)(Wh + (long)(kt + k) * 1024 + n0 + hf * 4);
            Bs[k][hf * 4 + 0] = b4.x;
            Bs[k][hf * 4 + 1] = b4.y;
            Bs[k][hf * 4 + 2] = b4.z;
            Bs[k][hf * 4 + 3] = b4.w;
        }
        __syncthreads();
#pragma unroll
        for (int kk = 0; kk < 16; kk++) {
            float4 a = *(const float4*)&As[kk][ty * 4];
            float b = Bs[kk][tx];
            ULL bb = pack2(b, b);
            fma2(acc01, pack2(a.x, a.y), bb);
            fma2(acc23, pack2(a.z, a.w), bb);
        }
        __syncthreads();
    }

    float2 v01 = unpack2(acc01), v23 = unpack2(acc23);
    g_q[(ty * 4 + 0) * 1024 + n0 + tx] = v01.x;
    g_q[(ty * 4 + 1) * 1024 + n0 + tx] = v01.y;
    g_q[(ty * 4 + 2) * 1024 + n0 + tx] = v23.x;
    g_q[(ty * 4 + 3) * 1024 + n0 + tx] = v23.y;
}

// ---------------------------------------------------------------------------
// scores[b][n] = sum_a v[a] * tanh(fproj_bf16[b][n][a] + q[b][a])
// grid (25, 128), warp per n
// ---------------------------------------------------------------------------
__global__ __launch_bounds__(256) void energy_kernel(const float* __restrict__ v)
{
    const int b = blockIdx.y;
    const int warp = threadIdx.x >> 5, lane = threadIdx.x & 31;
    const int n = blockIdx.x * 8 + warp;
    if (n >= 196) return;

    const __nv_bfloat16* fp = g_fprojb + (long)(b * 196 + n) * 1024;
    const float* q = g_q + b * 1024;

    float acc = 0.f;
#pragma unroll
    for (int i = 0; i < 4; i++) {
        const int k0 = i * 256 + lane * 8;
        uint4 raw = *(const uint4*)(fp + k0);
        float2 f0 = __bfloat1622float2(*reinterpret_cast<__nv_bfloat162*>(&raw.x));
        float2 f1 = __bfloat1622float2(*reinterpret_cast<__nv_bfloat162*>(&raw.y));
        float2 f2 = __bfloat1622float2(*reinterpret_cast<__nv_bfloat162*>(&raw.z));
        float2 f3 = __bfloat1622float2(*reinterpret_cast<__nv_bfloat162*>(&raw.w));
        float4 q0 = *(const float4*)(q + k0);
        float4 q1 = *(const float4*)(q + k0 + 4);
        float4 v0 = *(const float4*)(v + k0);
        float4 v1 = *(const float4*)(v + k0 + 4);
        acc = fmaf(v0.x, fast_tanh(f0.x + q0.x), acc);
        acc = fmaf(v0.y, fast_tanh(f0.y + q0.y), acc);
        acc = fmaf(v0.z, fast_tanh(f1.x + q0.z), acc);
        acc = fmaf(v0.w, fast_tanh(f1.y + q0.w), acc);
        acc = fmaf(v1.x, fast_tanh(f2.x + q1.x), acc);
        acc = fmaf(v1.y, fast_tanh(f2.y + q1.y), acc);
        acc = fmaf(v1.z, fast_tanh(f3.x + q1.z), acc);
        acc = fmaf(v1.w, fast_tanh(f3.y + q1.w), acc);
    }
#pragma unroll
    for (int o = 16; o; o >>= 1) acc += __shfl_xor_sync(0xffffffffu, acc, o);
    if (lane == 0) g_scores[b * 196 + n] = acc;
}

// ---------------------------------------------------------------------------
// softmax over n, then attn[b][f] = sum_n alpha[n] * feats_bf16[b][n][f]
// grid 128, 512 threads; each thread owns col pair (2*tid, 2*tid+1)
// ---------------------------------------------------------------------------
__global__ __launch_bounds__(512) void softmax_attn_kernel()
{
    const int b = blockIdx.x, tid = threadIdx.x;
    const int lane = tid & 31, warp = tid >> 5;
    __shared__ float sal[196];
    __shared__ float red[16];

    float s = (tid < 196) ? g_scores[b * 196 + tid] : -3.0e38f;

    float m = s;
#pragma unroll
    for (int o = 16; o; o >>= 1) m = fmaxf(m, __shfl_xor_sync(0xffffffffu, m, o));
    if (lane == 0) red[warp] = m;
    __syncthreads();
    if (tid == 0) {
        float t2 = red[0];
        for (int i = 1; i < 16; i++) t2 = fmaxf(t2, red[i]);
        red[0] = t2;
    }
    __syncthreads();
    const float M = red[0];
    __syncthreads();

    float e = (tid < 196) ? __expf(s - M) : 0.f;
    float sm = e;
#pragma unroll
    for (int o = 16; o; o >>= 1) sm += __shfl_xor_sync(0xffffffffu, sm, o);
    if (lane == 0) red[warp] = sm;
    __syncthreads();
    if (tid == 0) {
        float t2 = 0.f;
        for (int i = 0; i < 16; i++) t2 += red[i];
        red[0] = t2;
    }
    __syncthreads();
    const float S = red[0];
    if (tid < 196) sal[tid] = e / S;
    __syncthreads();

    const __nv_bfloat16* fb = g_featsb + (long)b * 196 * 1024;
    float a0 = 0.f, a1 = 0.f;
#pragma unroll 4
    for (int n = 0; n < 196; n++) {
        float al = sal[n];
        float2 f = __bfloat1622float2(*(const __nv_bfloat162*)(fb + n * 1024 + tid * 2));
        a0 = fmaf(al, f.x, a0);
        a1 = fmaf(al, f.y, a1);
    }
    g_attn[b * 1024 + tid * 2] = a0;
    g_attn[b * 1024 + tid * 2 + 1] = a1;
}

// ---------------------------------------------------------------------------
// gates[b][j] = pre0[t][b][j] + attn@W_ih0[:,1024:]^T + h0@W_hh0^T
// grid 128 (n-tiles BN=32), BM=128, full-K both phases, no atomics
// ---------------------------------------------------------------------------
__global__ __launch_bounds__(256) void gates_kernel(
    const float* __restrict__ W_ih0, const float* __restrict__ W_hh0, int t)
{
    __shared__ __align__(16) float As[8][128];
    __shared__ __align__(16) float Bs[8][32];

    const int tid = threadIdx.x;
    const int n0 = blockIdx.x * 32;
    const int ty = tid >> 3;   // rows ty*4..+3
    const int tx = tid & 7;    // cols tx*4..+3

    ULL acc[4][2];
#pragma unroll
    for (int i = 0; i < 4; i++) { acc[i][0] = 0ull; acc[i][1] = 0ull; }

    const int arow = tid >> 1, akq = tid & 1;
    const int bn = tid >> 3, bk = tid & 7;

#pragma unroll
    for (int p = 0; p < 2; p++) {
        const float* X = p ? g_h0 : g_attn;
        const float* W = p ? W_hh0 : (W_ih0 + 1024);
        const int ldw = p ? 1024 : 2048;
        const float* Aptr = X + arow * 1024 + akq * 4;
        const float* Bptr = W + (long)(n0 + bn) * ldw + bk;

        for (int kt = 0; kt < 1024; kt += 8) {
            float4 a4 = *(const float4*)(Aptr + kt);
            As[akq * 4 + 0][arow] = a4.x;
            As[akq * 4 + 1][arow] = a4.y;
            As[akq * 4 + 2][arow] = a4.z;
            As[akq * 4 + 3][arow] = a4.w;
            Bs[bk][bn] = Bptr[kt];
            __syncthreads();
#pragma unroll
            for (int kk = 0; kk < 8; kk++) {
                float4 a = *(const float4*)&As[kk][ty * 4];
                ulonglong2 bb = *(const ulonglong2*)&Bs[kk][tx * 4];
#pragma unroll
                for (int i = 0; i < 4; i++) {
                    float ai = (i == 0) ? a.x : (i == 1) ? a.y : (i == 2) ? a.z : a.w;
                    ULL ap = pack2(ai, ai);
                    fma2(acc[i][0], ap, bb.x);
                    fma2(acc[i][1], ap, bb.y);
                }
            }
            __syncthreads();
        }
    }

    const float* pre = g_pre0 + (long)t * 524288;
#pragma unroll
    for (int i = 0; i < 4; i++) {
        const int row = ty * 4 + i;
#pragma unroll
        for (int j = 0; j < 2; j++) {
            float2 vv = unpack2(acc[i][j]);
            const int col = n0 + tx * 4 + j * 2;
            g_gates[row * 4096 + col] = vv.x + pre[row * 4096 + col];
            g_gates[row * 4096 + col + 1] = vv.y + pre[row * 4096 + col + 1];
        }
    }
}

// ---------------------------------------------------------------------------
__global__ __launch_bounds__(256) void cell0_kernel(int t)
{
    const int idx = blockIdx.x * 256 + threadIdx.x;  // 131072
    const int b = idx >> 10, h = idx & 1023;
    const float* g = g_gates + b * 4096;
    float gi = g[h], gf = g[h + 1024], gg = g[h + 2048], go = g[h + 3072];
    float c = g_c0[idx];
    float cn = sigf(gf) * c + sigf(gi) * tanhf(gg);
    float hn = sigf(go) * tanhf(cn);
    g_c0[idx] = cn;
    g_h0[idx] = hn;
    g_c0all[t * 131072 + idx] = cn;
    g_h0all[t * 131072 + idx] = hn;
}

__global__ __launch_bounds__(256) void cell1_kernel(float* __restrict__ out)
{
    const int idx = blockIdx.x * 256 + threadIdx.x;  // 4194304
    const int m = idx >> 10, h = idx & 1023;
    const float* g = g_gates1 + (long)m * 4096;
    float gi = g[h], gf = g[h + 1024], gg = g[h + 2048], go = g[h + 3072];
    float c0n = g_c0all[idx];
    float c1 = sigf(gf) * c0n + sigf(gi) * tanhf(gg);
    float h1 = sigf(go) * tanhf(c1);
    const int b = m & 127, t = m >> 7;
    out[(long)(b * 32 + t) * 1024 + h] = h1;
}

// ---------------------------------------------------------------------------
__global__ __launch_bounds__(256) void prep_kernel(
    const float* __restrict__ W_ih1, const float* __restrict__ W_hh1,
    const float* __restrict__ b_ih0, const float* __restrict__ b_hh0,
    const float* __restrict__ b_ih1, const float* __restrict__ b_hh1)
{
    const int i = blockIdx.x * 256 + threadIdx.x;
    const int stride = gridDim.x * 256;
    for (int idx = i; idx < 4096 * 1024; idx += stride)
        g_w1c[idx] = W_ih1[idx] + W_hh1[idx];
    if (i < 4096) {
        g_b0c[i] = b_ih0[i] + b_hh0[i];
        g_b1c[i] = b_ih1[i] + b_hh1[i];
    }
}

__global__ __launch_bounds__(256) void conv_feats_kernel(const float* __restrict__ feats)
{
    const long i = ((long)blockIdx.x * 256 + threadIdx.x) * 4;  // 25088*1024 total
    float4 f = *(const float4*)(feats + i);
    *(__nv_bfloat162*)&g_featsb[i] = __float22bfloat162_rn(make_float2(f.x, f.y));
    *(__nv_bfloat162*)&g_featsb[i + 2] = __float22bfloat162_rn(make_float2(f.z, f.w));
}

// ---------------------------------------------------------------------------
extern "C" void kernel_launch(void* const* d_in, const int* in_sizes, int n_in,
                              void* d_out, int out_size)
{
    const float* feats = (const float*)d_in[0];
    const float* emb   = (const float*)d_in[1];
    const float* Wf    = (const float*)d_in[2];
    const float* Wh    = (const float*)d_in[3];
    const float* b_att = (const float*)d_in[4];
    const float* v     = (const float*)d_in[5];
    const float* W_ih0 = (const float*)d_in[6];
    const float* W_hh0 = (const float*)d_in[7];
    const float* b_ih0 = (const float*)d_in[8];
    const float* b_hh0 = (const float*)d_in[9];
    const float* W_ih1 = (const float*)d_in[10];
    const float* W_hh1 = (const float*)d_in[11];
    const float* b_ih1 = (const float*)d_in[12];
    const float* b_hh1 = (const float*)d_in[13];
    float* out = (float*)d_out;

    void *p_fprojb, *p_pre0, *p_w1c, *p_b0c, *p_b1c, *p_h0, *p_c0, *p_h0all, *p_gates1;
    cudaGetSymbolAddress(&p_fprojb, g_fprojb);
    cudaGetSymbolAddress(&p_pre0, g_pre0);
    cudaGetSymbolAddress(&p_w1c, g_w1c);
    cudaGetSymbolAddress(&p_b0c, g_b0c);
    cudaGetSymbolAddress(&p_b1c, g_b1c);
    cudaGetSymbolAddress(&p_h0, g_h0);
    cudaGetSymbolAddress(&p_c0, g_c0);
    cudaGetSymbolAddress(&p_h0all, g_h0all);
    cudaGetSymbolAddress(&p_gates1, g_gates1);

    prep_kernel<<<2048, 256>>>(W_ih1, W_hh1, b_ih0, b_hh0, b_ih1, b_hh1);
    conv_feats_kernel<<<25088, 256>>>(feats);

    // f_proj(bf16) = feats @ Wf + b_att
    gemm128_kernel<false, false, true, true><<<dim3(196, 8, 1), 256>>>(
        feats, 1024, Wf, 1024, p_fprojb, 1024, b_att, 1024);

    // pre0[t][b][:] = emb[b][t][:] @ W_ih0[:, :1024]^T + (b_ih0 + b_hh0)
    gemm128_kernel<true, true, true, false><<<dim3(32, 32, 1), 256>>>(
        emb, 1024, W_ih0, 2048, p_pre0, 4096, (const float*)p_b0c, 1024);

    cudaMemsetAsync(p_h0, 0, 128 * 1024 * sizeof(float));
    cudaMemsetAsync(p_c0, 0, 128 * 1024 * sizeof(float));

    for (int t = 0; t < 32; t++) {
        qgemm_kernel<<<128, 256>>>(Wh);
        energy_kernel<<<dim3(25, 128), 256>>>(v);
        softmax_attn_kernel<<<128, 512>>>();
        gates_kernel<<<128, 256>>>(W_ih0, W_hh0, t);
        cell0_kernel<<<512, 256>>>(t);
    }

    // batched layer 1: gates1 = h0all @ (W_ih1 + W_hh1)^T + (b_ih1 + b_hh1)
    gemm128_kernel<true, false, true, false><<<dim3(32, 32, 1), 256>>>(
        (const float*)p_h0all, 1024, (const float*)p_w1c, 1024,
        p_gates1, 4096, (const float*)p_b1c, 1024);

    cell1_kernel<<<16384, 256>>>(out);
}

// round 4
// speedup vs baseline: 1.8779x; 1.8779x over previous
#include <cuda_runtime.h>
#include <cuda_bf16.h>
#include <cstdint>

// ---------------------------------------------------------------------------
// B=128, T=32, N=196, E=FD=H=A=1024, 4H=4096, E+FD=2048
// Inputs: 0 feats[128,196,1024] 1 embeddings[128,32,1024] 2 Wf 3 Wh 4 b_att
//         5 v 6 W_ih0[4096,2048] 7 W_hh0[4096,1024] 8 b_ih0 9 b_hh0
//         10 W_ih1 11 W_hh1 12 b_ih1 13 b_hh1
// Output: [128,32,1024] fp32
// ---------------------------------------------------------------------------

// ------------------------------ scratch ------------------------------------
__device__ __nv_bfloat16 g_fprojb[25088 * 1024];   // [b][n][a] bf16   51.4 MB
__device__ __nv_bfloat16 g_featsb[25088 * 1024];   // feats bf16       51.4 MB
__device__ float g_pre0[32 * 128 * 4096];          // [t][b][j]        67.1 MB
__device__ float g_w0cat[4096 * 2048];             // [Wih0_attn|Whh0] 33.6 MB
__device__ float g_w1c[4096 * 1024];               // W_ih1+W_hh1      16.8 MB
__device__ float g_wfT[1024 * 1024];               // Wf^T  [a][f]
__device__ float g_whT[1024 * 1024];               // Wh^T  [a][h]
__device__ float g_b0c[4096];
__device__ float g_b1c[4096];
__device__ float g_x[128 * 2048];                  // [attn | h0] per b
__device__ float g_c0[128 * 1024];
__device__ float g_q[128 * 1024];
__device__ float g_scores[128 * 196];
__device__ float g_gates[128 * 4096];
__device__ float g_h0all[32 * 128 * 1024];         // [t][b][h]
__device__ float g_c0all[32 * 128 * 1024];
__device__ float g_gates1[32 * 128 * 4096];        // 67.1 MB

// ------------------------------ helpers ------------------------------------
__device__ __forceinline__ float fast_tanh(float x) {
    float r; asm("tanh.approx.f32 %0, %1;" : "=f"(r) : "f"(x)); return r;
}
__device__ __forceinline__ float sigf(float x) { return 1.f / (1.f + __expf(-x)); }
__device__ __forceinline__ uint32_t f2tf32(float x) {
    uint32_t r; asm("cvt.rna.tf32.f32 %0, %1;" : "=r"(r) : "f"(x)); return r;
}
__device__ __forceinline__ void mma_tf32(float* c, const uint32_t* a, const uint32_t* b) {
    asm volatile(
        "mma.sync.aligned.m16n8k8.row.col.f32.tf32.tf32.f32 "
        "{%0,%1,%2,%3}, {%4,%5,%6,%7}, {%8,%9}, {%0,%1,%2,%3};"
        : "+f"(c[0]), "+f"(c[1]), "+f"(c[2]), "+f"(c[3])
        : "r"(a[0]), "r"(a[1]), "r"(a[2]), "r"(a[3]), "r"(b[0]), "r"(b[1]));
}

// ---------------------------------------------------------------------------
// Universal tf32 MMA GEMM:  C[M,N] = A[M,K] * B[N,K]^T  (+bias) (+pre)
//   PERM: A row m reads source row (m%128)*32 + m/128
//   OUTBF: C stored bf16, else fp32
// Block: BM x BN, 256 threads = 8 warps in 4x2 grid (WM=BM/4, WN=BN/2).
// k-chunk 16 (two k8 mma steps), single-buffer smem + register prefetch.
// ---------------------------------------------------------------------------
template <int BM, int BN, bool PERM, bool BIAS, bool OUTBF, bool ADDPRE>
__global__ __launch_bounds__(256) void mma_gemm(
    const float* __restrict__ A, int lda,
    const float* __restrict__ B, int ldb,
    void* __restrict__ Cv, int ldc,
    const float* __restrict__ bias,
    const float* __restrict__ pre,
    int K)
{
    constexpr int KC = 16;
    constexpr int PAD = 20;                 // bank-conflict-free for frag reads
    constexpr int WM = BM / 4;              // 32
    constexpr int WN = BN / 2;              // 64 (BN=128) or 16 (BN=32)
    constexpr int MFR = WM / 16;            // 2
    constexpr int NFR = WN / 8;             // 8 or 2
    constexpr int ATOT = BM * KC / 4;       // float4 count for A tile
    constexpr int BTOT = BN * KC / 4;
    constexpr int ALD = (ATOT + 255) / 256;
    constexpr int BLD = (BTOT + 255) / 256;

    __shared__ float As[BM][PAD];
    __shared__ float Bs[BN][PAD];

    const int tid = threadIdx.x;
    const int wid = tid >> 5, lane = tid & 31;
    const int m0 = blockIdx.x * BM;
    const int n0 = blockIdx.y * BN;
    const int wm = (wid & 3) * WM;
    const int wn = (wid >> 2) * WN;
    const int g = lane >> 2, tg = lane & 3;

    float acc[MFR][NFR][4];
#pragma unroll
    for (int i = 0; i < MFR; i++)
#pragma unroll
        for (int j = 0; j < NFR; j++)
#pragma unroll
            for (int k = 0; k < 4; k++) acc[i][j][k] = 0.f;

    float4 pa[ALD], pb[BLD];

    // prefetch tile 0
#pragma unroll
    for (int i = 0; i < ALD; i++) {
        int idx = tid + i * 256;
        if (ATOT <= 256 * ALD && idx < ATOT) {
            int row = idx >> 2, kq = idx & 3;
            int ar = m0 + row;
            if (PERM) ar = (ar & 127) * 32 + (ar >> 7);
            pa[i] = *(const float4*)(A + (long)ar * lda + kq * 4);
        }
    }
#pragma unroll
    for (int i = 0; i < BLD; i++) {
        int idx = tid + i * 256;
        if (idx < BTOT) {
            int row = idx >> 2, kq = idx & 3;
            pb[i] = *(const float4*)(B + (long)(n0 + row) * ldb + kq * 4);
        }
    }

    for (int kt = 0; kt < K; kt += KC) {
        __syncthreads();
        // store (tf32-converted) to smem
#pragma unroll
        for (int i = 0; i < ALD; i++) {
            int idx = tid + i * 256;
            if (idx < ATOT) {
                int row = idx >> 2, kq = idx & 3;
                As[row][kq * 4 + 0] = __uint_as_float(f2tf32(pa[i].x));
                As[row][kq * 4 + 1] = __uint_as_float(f2tf32(pa[i].y));
                As[row][kq * 4 + 2] = __uint_as_float(f2tf32(pa[i].z));
                As[row][kq * 4 + 3] = __uint_as_float(f2tf32(pa[i].w));
            }
        }
#pragma unroll
        for (int i = 0; i < BLD; i++) {
            int idx = tid + i * 256;
            if (idx < BTOT) {
                int row = idx >> 2, kq = idx & 3;
                Bs[row][kq * 4 + 0] = __uint_as_float(f2tf32(pb[i].x));
                Bs[row][kq * 4 + 1] = __uint_as_float(f2tf32(pb[i].y));
                Bs[row][kq * 4 + 2] = __uint_as_float(f2tf32(pb[i].z));
                Bs[row][kq * 4 + 3] = __uint_as_float(f2tf32(pb[i].w));
            }
        }
        __syncthreads();

        // prefetch next tile
        if (kt + KC < K) {
#pragma unroll
            for (int i = 0; i < ALD; i++) {
                int idx = tid + i * 256;
                if (idx < ATOT) {
                    int row = idx >> 2, kq = idx & 3;
                    int ar = m0 + row;
                    if (PERM) ar = (ar & 127) * 32 + (ar >> 7);
                    pa[i] = *(const float4*)(A + (long)ar * lda + kt + KC + kq * 4);
                }
            }
#pragma unroll
            for (int i = 0; i < BLD; i++) {
                int idx = tid + i * 256;
                if (idx < BTOT) {
                    int row = idx >> 2, kq = idx & 3;
                    pb[i] = *(const float4*)(B + (long)(n0 + row) * ldb + kt + KC + kq * 4);
                }
            }
        }

        // compute: two k8 steps
#pragma unroll
        for (int ko = 0; ko < KC; ko += 8) {
            uint32_t af[MFR][4];
#pragma unroll
            for (int f = 0; f < MFR; f++) {
                int r = wm + f * 16;
                af[f][0] = __float_as_uint(As[r + g][ko + tg]);
                af[f][1] = __float_as_uint(As[r + g + 8][ko + tg]);
                af[f][2] = __float_as_uint(As[r + g][ko + tg + 4]);
                af[f][3] = __float_as_uint(As[r + g + 8][ko + tg + 4]);
            }
            uint32_t bf[NFR][2];
#pragma unroll
            for (int nf = 0; nf < NFR; nf++) {
                int r = wn + nf * 8 + g;
                bf[nf][0] = __float_as_uint(Bs[r][ko + tg]);
                bf[nf][1] = __float_as_uint(Bs[r][ko + tg + 4]);
            }
#pragma unroll
            for (int f = 0; f < MFR; f++)
#pragma unroll
                for (int nf = 0; nf < NFR; nf++)
                    mma_tf32(acc[f][nf], af[f], bf[nf]);
        }
    }

    // epilogue
#pragma unroll
    for (int f = 0; f < MFR; f++) {
#pragma unroll
        for (int nf = 0; nf < NFR; nf++) {
            const int col = n0 + wn + nf * 8 + tg * 2;
#pragma unroll
            for (int h = 0; h < 2; h++) {   // h=0: row g, h=1: row g+8
                const long row = m0 + wm + f * 16 + g + h * 8;
                float v0 = acc[f][nf][h * 2 + 0];
                float v1 = acc[f][nf][h * 2 + 1];
                if (BIAS) { v0 += bias[col]; v1 += bias[col + 1]; }
                if (ADDPRE) {
                    v0 += pre[row * ldc + col];
                    v1 += pre[row * ldc + col + 1];
                }
                if (OUTBF) {
                    __nv_bfloat16* Cb = (__nv_bfloat16*)Cv;
                    *(__nv_bfloat162*)&Cb[row * ldc + col] =
                        __float22bfloat162_rn(make_float2(v0, v1));
                } else {
                    float* Cf = (float*)Cv;
                    Cf[row * ldc + col] = v0;
                    Cf[row * ldc + col + 1] = v1;
                }
            }
        }
    }
}

// ---------------------------------------------------------------------------
// scores[b][n] = sum_a v[a] * tanh(fproj_bf16[b][n][a] + q[b][a])
// ---------------------------------------------------------------------------
__global__ __launch_bounds__(256) void energy_kernel(const float* __restrict__ v)
{
    const int b = blockIdx.y;
    const int warp = threadIdx.x >> 5, lane = threadIdx.x & 31;
    const int n = blockIdx.x * 8 + warp;
    if (n >= 196) return;

    const __nv_bfloat16* fp = g_fprojb + (long)(b * 196 + n) * 1024;
    const float* q = g_q + b * 1024;

    float acc = 0.f;
#pragma unroll
    for (int i = 0; i < 4; i++) {
        const int k0 = i * 256 + lane * 8;
        uint4 raw = *(const uint4*)(fp + k0);
        float2 f0 = __bfloat1622float2(*reinterpret_cast<__nv_bfloat162*>(&raw.x));
        float2 f1 = __bfloat1622float2(*reinterpret_cast<__nv_bfloat162*>(&raw.y));
        float2 f2 = __bfloat1622float2(*reinterpret_cast<__nv_bfloat162*>(&raw.z));
        float2 f3 = __bfloat1622float2(*reinterpret_cast<__nv_bfloat162*>(&raw.w));
        float4 q0 = *(const float4*)(q + k0);
        float4 q1 = *(const float4*)(q + k0 + 4);
        float4 v0 = *(const float4*)(v + k0);
        float4 v1 = *(const float4*)(v + k0 + 4);
        acc = fmaf(v0.x, fast_tanh(f0.x + q0.x), acc);
        acc = fmaf(v0.y, fast_tanh(f0.y + q0.y), acc);
        acc = fmaf(v0.z, fast_tanh(f1.x + q0.z), acc);
        acc = fmaf(v0.w, fast_tanh(f1.y + q0.w), acc);
        acc = fmaf(v1.x, fast_tanh(f2.x + q1.x), acc);
        acc = fmaf(v1.y, fast_tanh(f2.y + q1.y), acc);
        acc = fmaf(v1.z, fast_tanh(f3.x + q1.z), acc);
        acc = fmaf(v1.w, fast_tanh(f3.y + q1.w), acc);
    }
#pragma unroll
    for (int o = 16; o; o >>= 1) acc += __shfl_xor_sync(0xffffffffu, acc, o);
    if (lane == 0) g_scores[b * 196 + n] = acc;
}

// ---------------------------------------------------------------------------
// softmax over n, then attn (into g_x[:, 0:1024])
// ---------------------------------------------------------------------------
__global__ __launch_bounds__(512) void softmax_attn_kernel()
{
    const int b = blockIdx.x, tid = threadIdx.x;
    const int lane = tid & 31, warp = tid >> 5;
    __shared__ float sal[196];
    __shared__ float red[16];

    float s = (tid < 196) ? g_scores[b * 196 + tid] : -3.0e38f;

    float m = s;
#pragma unroll
    for (int o = 16; o; o >>= 1) m = fmaxf(m, __shfl_xor_sync(0xffffffffu, m, o));
    if (lane == 0) red[warp] = m;
    __syncthreads();
    if (tid == 0) {
        float t2 = red[0];
        for (int i = 1; i < 16; i++) t2 = fmaxf(t2, red[i]);
        red[0] = t2;
    }
    __syncthreads();
    const float M = red[0];
    __syncthreads();

    float e = (tid < 196) ? __expf(s - M) : 0.f;
    float sm = e;
#pragma unroll
    for (int o = 16; o; o >>= 1) sm += __shfl_xor_sync(0xffffffffu, sm, o);
    if (lane == 0) red[warp] = sm;
    __syncthreads();
    if (tid == 0) {
        float t2 = 0.f;
        for (int i = 0; i < 16; i++) t2 += red[i];
        red[0] = t2;
    }
    __syncthreads();
    const float S = red[0];
    if (tid < 196) sal[tid] = e / S;
    __syncthreads();

    const __nv_bfloat16* fb = g_featsb + (long)b * 196 * 1024;
    float a0 = 0.f, a1 = 0.f;
#pragma unroll 4
    for (int n = 0; n < 196; n++) {
        float al = sal[n];
        float2 f = __bfloat1622float2(*(const __nv_bfloat162*)(fb + n * 1024 + tid * 2));
        a0 = fmaf(al, f.x, a0);
        a1 = fmaf(al, f.y, a1);
    }
    g_x[b * 2048 + tid * 2] = a0;
    g_x[b * 2048 + tid * 2 + 1] = a1;
}

// ---------------------------------------------------------------------------
__global__ __launch_bounds__(256) void cell0_kernel(int t)
{
    const int idx = blockIdx.x * 256 + threadIdx.x;  // 131072
    const int b = idx >> 10, h = idx & 1023;
    const float* g = g_gates + b * 4096;
    float gi = g[h], gf = g[h + 1024], gg = g[h + 2048], go = g[h + 3072];
    float c = g_c0[idx];
    float cn = sigf(gf) * c + sigf(gi) * tanhf(gg);
    float hn = sigf(go) * tanhf(cn);
    g_c0[idx] = cn;
    g_x[b * 2048 + 1024 + h] = hn;
    g_c0all[t * 131072 + idx] = cn;
    g_h0all[t * 131072 + idx] = hn;
}

__global__ __launch_bounds__(256) void cell1_kernel(float* __restrict__ out)
{
    const int idx = blockIdx.x * 256 + threadIdx.x;  // 4194304
    const int m = idx >> 10, h = idx & 1023;
    const float* g = g_gates1 + (long)m * 4096;
    float gi = g[h], gf = g[h + 1024], gg = g[h + 2048], go = g[h + 3072];
    float c0n = g_c0all[idx];
    float c1 = sigf(gf) * c0n + sigf(gi) * tanhf(gg);
    float h1 = sigf(go) * tanhf(c1);
    const int b = m & 127, t = m >> 7;
    out[(long)(b * 32 + t) * 1024 + h] = h1;
}

// ---------------------------------------------------------------------------
// prep: w0cat, w1c, biases
// ---------------------------------------------------------------------------
__global__ __launch_bounds__(256) void prep_kernel(
    const float* __restrict__ W_ih0, const float* __restrict__ W_hh0,
    const float* __restrict__ W_ih1, const float* __restrict__ W_hh1,
    const float* __restrict__ b_ih0, const float* __restrict__ b_hh0,
    const float* __restrict__ b_ih1, const float* __restrict__ b_hh1)
{
    const int i = blockIdx.x * 256 + threadIdx.x;
    const int stride = gridDim.x * 256;
    for (int idx = i; idx < 4096 * 2048; idx += stride) {
        const int n = idx >> 11, k = idx & 2047;
        g_w0cat[idx] = (k < 1024) ? W_ih0[n * 2048 + 1024 + k]
                                  : W_hh0[n * 1024 + (k - 1024)];
    }
    for (int idx = i; idx < 4096 * 1024; idx += stride)
        g_w1c[idx] = W_ih1[idx] + W_hh1[idx];
    if (i < 4096) {
        g_b0c[i] = b_ih0[i] + b_hh0[i];
        g_b1c[i] = b_ih1[i] + b_hh1[i];
    }
}

__global__ void transpose_kernel(const float* __restrict__ src, float* __restrict__ dst)
{
    __shared__ float tile[32][33];
    int x = blockIdx.x * 32 + threadIdx.x;
    int y = blockIdx.y * 32 + threadIdx.y;
    tile[threadIdx.y][threadIdx.x] = src[y * 1024 + x];
    __syncthreads();
    x = blockIdx.y * 32 + threadIdx.x;
    y = blockIdx.x * 32 + threadIdx.y;
    dst[y * 1024 + x] = tile[threadIdx.x][threadIdx.y];
}

__global__ __launch_bounds__(256) void conv_feats_kernel(const float* __restrict__ feats)
{
    const long i = ((long)blockIdx.x * 256 + threadIdx.x) * 4;
    float4 f = *(const float4*)(feats + i);
    *(__nv_bfloat162*)&g_featsb[i] = __float22bfloat162_rn(make_float2(f.x, f.y));
    *(__nv_bfloat162*)&g_featsb[i + 2] = __float22bfloat162_rn(make_float2(f.z, f.w));
}

// ---------------------------------------------------------------------------
extern "C" void kernel_launch(void* const* d_in, const int* in_sizes, int n_in,
                              void* d_out, int out_size)
{
    const float* feats = (const float*)d_in[0];
    const float* emb   = (const float*)d_in[1];
    const float* Wf    = (const float*)d_in[2];
    const float* Wh    = (const float*)d_in[3];
    const float* b_att = (const float*)d_in[4];
    const float* v     = (const float*)d_in[5];
    const float* W_ih0 = (const float*)d_in[6];
    const float* W_hh0 = (const float*)d_in[7];
    const float* b_ih0 = (const float*)d_in[8];
    const float* b_hh0 = (const float*)d_in[9];
    const float* W_ih1 = (const float*)d_in[10];
    const float* W_hh1 = (const float*)d_in[11];
    const float* b_ih1 = (const float*)d_in[12];
    const float* b_hh1 = (const float*)d_in[13];
    float* out = (float*)d_out;

    void *p_fprojb, *p_pre0, *p_w0cat, *p_w1c, *p_wfT, *p_whT, *p_b0c, *p_b1c;
    void *p_x, *p_c0, *p_q, *p_gates, *p_h0all, *p_gates1;
    cudaGetSymbolAddress(&p_fprojb, g_fprojb);
    cudaGetSymbolAddress(&p_pre0, g_pre0);
    cudaGetSymbolAddress(&p_w0cat, g_w0cat);
    cudaGetSymbolAddress(&p_w1c, g_w1c);
    cudaGetSymbolAddress(&p_wfT, g_wfT);
    cudaGetSymbolAddress(&p_whT, g_whT);
    cudaGetSymbolAddress(&p_b0c, g_b0c);
    cudaGetSymbolAddress(&p_b1c, g_b1c);
    cudaGetSymbolAddress(&p_x, g_x);
    cudaGetSymbolAddress(&p_c0, g_c0);
    cudaGetSymbolAddress(&p_q, g_q);
    cudaGetSymbolAddress(&p_gates, g_gates);
    cudaGetSymbolAddress(&p_h0all, g_h0all);
    cudaGetSymbolAddress(&p_gates1, g_gates1);

    prep_kernel<<<2048, 256>>>(W_ih0, W_hh0, W_ih1, W_hh1, b_ih0, b_hh0, b_ih1, b_hh1);
    transpose_kernel<<<dim3(32, 32), dim3(32, 32)>>>(Wf, (float*)p_wfT);
    transpose_kernel<<<dim3(32, 32), dim3(32, 32)>>>(Wh, (float*)p_whT);
    conv_feats_kernel<<<25088, 256>>>(feats);

    // f_proj(bf16) = feats @ Wf + b_att   (B = Wf^T in [N,K])
    mma_gemm<128, 128, false, true, true, false><<<dim3(196, 8), 256>>>(
        feats, 1024, (const float*)p_wfT, 1024, p_fprojb, 1024, b_att, nullptr, 1024);

    // pre0[t*128+b][:] = emb[b][t][:] @ W_ih0[:, :1024]^T + b0c
    mma_gemm<128, 128, true, true, false, false><<<dim3(32, 32), 256>>>(
        emb, 1024, W_ih0, 2048, p_pre0, 4096, (const float*)p_b0c, nullptr, 1024);

    cudaMemsetAsync(p_x, 0, 128 * 2048 * sizeof(float));
    cudaMemsetAsync(p_c0, 0, 128 * 1024 * sizeof(float));

    for (int t = 0; t < 32; t++) {
        // q = h0 @ Wh   (A = g_x[:,1024:], B = Wh^T)
        mma_gemm<128, 32, false, false, false, false><<<dim3(1, 32), 256>>>(
            (const float*)p_x + 1024, 2048, (const float*)p_whT, 1024,
            p_q, 1024, nullptr, nullptr, 1024);

        energy_kernel<<<dim3(25, 128), 256>>>(v);
        softmax_attn_kernel<<<128, 512>>>();

        // gates = [attn|h0] @ w0cat^T + pre0_t
        mma_gemm<128, 32, false, false, false, true><<<dim3(1, 128), 256>>>(
            (const float*)p_x, 2048, (const float*)p_w0cat, 2048,
            p_gates, 4096, nullptr, (const float*)p_pre0 + (size_t)t * 524288, 2048);

        cell0_kernel<<<512, 256>>>(t);
    }

    // batched layer 1: gates1 = h0all @ (W_ih1 + W_hh1)^T + b1c
    mma_gemm<128, 128, false, true, false, false><<<dim3(32, 32), 256>>>(
        (const float*)p_h0all, 1024, (const float*)p_w1c, 1024,
        p_gates1, 4096, (const float*)p_b1c, nullptr, 1024);

    cell1_kernel<<<16384, 256>>>(out);
}

// round 5
// speedup vs baseline: 2.6658x; 1.4196x over previous
#include <cuda_runtime.h>
#include <cuda_bf16.h>
#include <cstdint>

// ---------------------------------------------------------------------------
// B=128, T=32, N=196, E=FD=H=A=1024, 4H=4096, E+FD=2048
// ---------------------------------------------------------------------------

// ------------------------------ scratch ------------------------------------
__device__ __nv_bfloat16 g_fprojb[25088 * 1024];   // bf16 f_proj      51.4 MB
__device__ __nv_bfloat16 g_featsb[25088 * 1024];   // bf16 feats       51.4 MB
__device__ float g_featsr[25088 * 1024];           // tf32 feats      102.8 MB
__device__ float g_embp[4096 * 1024];              // perm+tf32 emb    16.8 MB
__device__ float g_pre0[32 * 128 * 4096];          // fp32             67.1 MB
__device__ float g_w0cat[4096 * 2048];             // tf32 [Wih0a|Whh0]33.6 MB
__device__ float g_w0e[4096 * 1024];               // tf32 Wih0 embed  16.8 MB
__device__ float g_w1c[4096 * 1024];               // tf32 Wih1+Whh1   16.8 MB
__device__ float g_wfT[1024 * 1024];               // tf32 Wf^T
__device__ float g_whT[1024 * 1024];               // tf32 Wh^T
__device__ float g_b0c[4096];
__device__ float g_b1c[4096];
__device__ float g_x[128 * 2048];                  // tf32 [attn | h0]
__device__ float g_c0[128 * 1024];
__device__ float g_qpart[4 * 128 * 1024];          // q split-K partials
__device__ float g_gpart[2 * 128 * 4096];          // gates split-K partials
__device__ float g_h0all[32 * 128 * 1024];         // tf32 [t][b][h]
__device__ float g_c0all[32 * 128 * 1024];         // fp32
__device__ float g_gates1[32 * 128 * 4096];        // 67.1 MB

// ------------------------------ helpers ------------------------------------
__device__ __forceinline__ float fast_tanh(float x) {
    float r; asm("tanh.approx.f32 %0, %1;" : "=f"(r) : "f"(x)); return r;
}
__device__ __forceinline__ float sigf(float x) { return 1.f / (1.f + __expf(-x)); }
__device__ __forceinline__ float rnd_tf32(float x) {
    uint32_t r; asm("cvt.rna.tf32.f32 %0, %1;" : "=r"(r) : "f"(x));
    return __uint_as_float(r);
}
__device__ __forceinline__ void mma_tf32(float* c, const uint32_t* a, const uint32_t* b) {
    asm volatile(
        "mma.sync.aligned.m16n8k8.row.col.f32.tf32.tf32.f32 "
        "{%0,%1,%2,%3}, {%4,%5,%6,%7}, {%8,%9}, {%0,%1,%2,%3};"
        : "+f"(c[0]), "+f"(c[1]), "+f"(c[2]), "+f"(c[3])
        : "r"(a[0]), "r"(a[1]), "r"(a[2]), "r"(a[3]), "r"(b[0]), "r"(b[1]));
}
__device__ __forceinline__ uint32_t smem_u32(const void* p) {
    return (uint32_t)__cvta_generic_to_shared(p);
}
__device__ __forceinline__ void cp16(uint32_t dst, const void* src) {
    asm volatile("cp.async.cg.shared.global [%0], [%1], 16;" :: "r"(dst), "l"(src));
}

// ---------------------------------------------------------------------------
// tf32 MMA GEMM v2: C[M,N] = A[M,K] * B[N,K]^T (+bias) (+pre, z==0 only)
// Operands MUST be pre-rounded to tf32. cp.async double-buffered, KC=32.
// BM=128 fixed. 256 threads, 8 warps 4x2 (WM=32, WN=BN/2).
// grid = (M/128, N/BN, kSplits);  per-split K = Ksplit, out += z*partStride.
// ---------------------------------------------------------------------------
template <int BN, bool BIAS, bool OUTBF, bool ADDPRE>
__global__ __launch_bounds__(256) void mma_gemm2(
    const float* __restrict__ A, int lda,
    const float* __restrict__ B, int ldb,
    void* __restrict__ Cv, int ldc,
    const float* __restrict__ bias,
    const float* __restrict__ pre,
    int Ksplit, long partStride)
{
    constexpr int KC = 32;
    constexpr int PITCH = 36;                 // conflict-free, 16B-aligned rows
    constexpr int WN = BN / 2;
    constexpr int NFR = WN / 8;
    constexpr int ASZ = 128 * PITCH;
    constexpr int BSZ = BN * PITCH;
    constexpr int BCH = BN * 8 / 256;         // B 16B-chunks per thread

    extern __shared__ float sm[];
    float* const Ab[2] = { sm, sm + ASZ };
    float* const Bb[2] = { sm + 2 * ASZ, sm + 2 * ASZ + BSZ };

    const int tid = threadIdx.x;
    const int wid = tid >> 5, lane = tid & 31;
    const int m0 = blockIdx.x * 128;
    const int n0 = blockIdx.y * BN;
    const int z = blockIdx.z;
    const long koff = (long)z * Ksplit;
    const int wm = (wid & 3) * 32;
    const int wn = (wid >> 2) * WN;
    const int g = lane >> 2, tg = lane & 3;
    const int NIT = Ksplit / KC;

    float acc[2][NFR][4];
#pragma unroll
    for (int f = 0; f < 2; f++)
#pragma unroll
        for (int j = 0; j < NFR; j++)
#pragma unroll
            for (int k = 0; k < 4; k++) acc[f][j][k] = 0.f;

    auto issue = [&](int it) {
        const int s = it & 1;
        const long kb = koff + (long)it * KC;
        float* As = Ab[s];
        float* Bs = Bb[s];
#pragma unroll
        for (int i = 0; i < 4; i++) {
            int c = tid + i * 256;
            int row = c >> 3, kq = c & 7;
            cp16(smem_u32(As + row * PITCH + kq * 4),
                 A + (long)(m0 + row) * lda + kb + kq * 4);
        }
#pragma unroll
        for (int i = 0; i < BCH; i++) {
            int c = tid + i * 256;
            int row = c >> 3, kq = c & 7;
            cp16(smem_u32(Bs + row * PITCH + kq * 4),
                 B + (long)(n0 + row) * ldb + kb + kq * 4);
        }
        asm volatile("cp.async.commit_group;" ::: "memory");
    };

    issue(0);
    for (int it = 0; it < NIT; it++) {
        asm volatile("cp.async.wait_group 0;" ::: "memory");
        __syncthreads();
        if (it + 1 < NIT) issue(it + 1);
        const float* As = Ab[it & 1];
        const float* Bs = Bb[it & 1];
#pragma unroll
        for (int ko = 0; ko < KC; ko += 8) {
            uint32_t af[2][4];
#pragma unroll
            for (int f = 0; f < 2; f++) {
                const int r = wm + f * 16;
                af[f][0] = __float_as_uint(As[(r + g) * PITCH + ko + tg]);
                af[f][1] = __float_as_uint(As[(r + g + 8) * PITCH + ko + tg]);
                af[f][2] = __float_as_uint(As[(r + g) * PITCH + ko + tg + 4]);
                af[f][3] = __float_as_uint(As[(r + g + 8) * PITCH + ko + tg + 4]);
            }
            uint32_t bf[NFR][2];
#pragma unroll
            for (int nf = 0; nf < NFR; nf++) {
                const int r = wn + nf * 8 + g;
                bf[nf][0] = __float_as_uint(Bs[r * PITCH + ko + tg]);
                bf[nf][1] = __float_as_uint(Bs[r * PITCH + ko + tg + 4]);
            }
#pragma unroll
            for (int f = 0; f < 2; f++)
#pragma unroll
                for (int nf = 0; nf < NFR; nf++)
                    mma_tf32(acc[f][nf], af[f], bf[nf]);
        }
        __syncthreads();
    }

    // epilogue
#pragma unroll
    for (int f = 0; f < 2; f++) {
#pragma unroll
        for (int nf = 0; nf < NFR; nf++) {
            const int col = n0 + wn + nf * 8 + tg * 2;
#pragma unroll
            for (int h = 0; h < 2; h++) {
                const long row = m0 + wm + f * 16 + g + h * 8;
                float v0 = acc[f][nf][h * 2 + 0];
                float v1 = acc[f][nf][h * 2 + 1];
                if (BIAS) { v0 += bias[col]; v1 += bias[col + 1]; }
                if (ADDPRE && z == 0) {
                    v0 += pre[row * ldc + col];
                    v1 += pre[row * ldc + col + 1];
                }
                if (OUTBF) {
                    __nv_bfloat16* Cb = (__nv_bfloat16*)Cv + z * partStride;
                    *(__nv_bfloat162*)&Cb[row * ldc + col] =
                        __float22bfloat162_rn(make_float2(v0, v1));
                } else {
                    float* Cf = (float*)Cv + z * partStride;
                    Cf[row * ldc + col] = v0;
                    Cf[row * ldc + col + 1] = v1;
                }
            }
        }
    }
}

// ---------------------------------------------------------------------------
// Fused per-b attention: q = sum of 4 partials; energies + tanh; softmax;
// attn = alpha @ feats; writes tf32-rounded attn into g_x[:, 0:1024].
// grid 128, 512 threads.
// ---------------------------------------------------------------------------
__global__ __launch_bounds__(512) void attn_fused(const float* __restrict__ v)
{
    const int b = blockIdx.x, tid = threadIdx.x;
    const int warp = tid >> 5, lane = tid & 31;
    __shared__ float qs[1024];
    __shared__ float sal[256];
    __shared__ float red[16];

    // fold q split-K partials
    for (int a = tid; a < 1024; a += 512) {
        qs[a] = g_qpart[b * 1024 + a] + g_qpart[131072 + b * 1024 + a]
              + g_qpart[262144 + b * 1024 + a] + g_qpart[393216 + b * 1024 + a];
    }
    __syncthreads();

    // energies: 16 warps stride the 196 rows
    for (int n = warp; n < 196; n += 16) {
        const __nv_bfloat16* fp = g_fprojb + (long)(b * 196 + n) * 1024;
        float acc = 0.f;
#pragma unroll
        for (int i = 0; i < 4; i++) {
            const int k0 = i * 256 + lane * 8;
            uint4 raw = *(const uint4*)(fp + k0);
            float2 f0 = __bfloat1622float2(*reinterpret_cast<__nv_bfloat162*>(&raw.x));
            float2 f1 = __bfloat1622float2(*reinterpret_cast<__nv_bfloat162*>(&raw.y));
            float2 f2 = __bfloat1622float2(*reinterpret_cast<__nv_bfloat162*>(&raw.z));
            float2 f3 = __bfloat1622float2(*reinterpret_cast<__nv_bfloat162*>(&raw.w));
            float4 q0 = *(const float4*)(qs + k0);
            float4 q1 = *(const float4*)(qs + k0 + 4);
            float4 v0 = *(const float4*)(v + k0);
            float4 v1 = *(const float4*)(v + k0 + 4);
            acc = fmaf(v0.x, fast_tanh(f0.x + q0.x), acc);
            acc = fmaf(v0.y, fast_tanh(f0.y + q0.y), acc);
            acc = fmaf(v0.z, fast_tanh(f1.x + q0.z), acc);
            acc = fmaf(v0.w, fast_tanh(f1.y + q0.w), acc);
            acc = fmaf(v1.x, fast_tanh(f2.x + q1.x), acc);
            acc = fmaf(v1.y, fast_tanh(f2.y + q1.y), acc);
            acc = fmaf(v1.z, fast_tanh(f3.x + q1.z), acc);
            acc = fmaf(v1.w, fast_tanh(f3.y + q1.w), acc);
        }
#pragma unroll
        for (int o = 16; o; o >>= 1) acc += __shfl_xor_sync(0xffffffffu, acc, o);
        if (lane == 0) sal[n] = acc;
    }
    __syncthreads();

    // softmax over 196
    float s = (tid < 196) ? sal[tid] : -3.0e38f;
    float m = s;
#pragma unroll
    for (int o = 16; o; o >>= 1) m = fmaxf(m, __shfl_xor_sync(0xffffffffu, m, o));
    if (lane == 0) red[warp] = m;
    __syncthreads();
    if (tid == 0) {
        float t2 = red[0];
        for (int i = 1; i < 16; i++) t2 = fmaxf(t2, red[i]);
        red[0] = t2;
    }
    __syncthreads();
    const float M = red[0];
    __syncthreads();

    float e = (tid < 196) ? __expf(s - M) : 0.f;
    float sm2 = e;
#pragma unroll
    for (int o = 16; o; o >>= 1) sm2 += __shfl_xor_sync(0xffffffffu, sm2, o);
    if (lane == 0) red[warp] = sm2;
    __syncthreads();
    if (tid == 0) {
        float t2 = 0.f;
        for (int i = 0; i < 16; i++) t2 += red[i];
        red[0] = t2;
    }
    __syncthreads();
    const float S = red[0];
    __syncthreads();
    if (tid < 196) sal[tid] = e / S;
    __syncthreads();

    // attn
    const __nv_bfloat16* fb = g_featsb + (long)b * 196 * 1024;
    float a0 = 0.f, a1 = 0.f;
#pragma unroll 4
    for (int n = 0; n < 196; n++) {
        float al = sal[n];
        float2 f = __bfloat1622float2(*(const __nv_bfloat162*)(fb + n * 1024 + tid * 2));
        a0 = fmaf(al, f.x, a0);
        a1 = fmaf(al, f.y, a1);
    }
    g_x[b * 2048 + tid * 2] = rnd_tf32(a0);
    g_x[b * 2048 + tid * 2 + 1] = rnd_tf32(a1);
}

// ---------------------------------------------------------------------------
__global__ __launch_bounds__(256) void cell0_kernel(int t)
{
    const int idx = blockIdx.x * 256 + threadIdx.x;  // 131072
    const int b = idx >> 10, h = idx & 1023;
    const float* g0 = g_gpart + b * 4096;
    const float* g1 = g_gpart + 524288 + b * 4096;
    float gi = g0[h] + g1[h];
    float gf = g0[h + 1024] + g1[h + 1024];
    float gg = g0[h + 2048] + g1[h + 2048];
    float go = g0[h + 3072] + g1[h + 3072];
    float c = g_c0[idx];
    float cn = sigf(gf) * c + sigf(gi) * tanhf(gg);
    float hn = sigf(go) * tanhf(cn);
    float hr = rnd_tf32(hn);
    g_c0[idx] = cn;
    g_x[b * 2048 + 1024 + h] = hr;
    g_c0all[t * 131072 + idx] = cn;
    g_h0all[t * 131072 + idx] = hr;
}

__global__ __launch_bounds__(256) void cell1_kernel(float* __restrict__ out)
{
    const int idx = blockIdx.x * 256 + threadIdx.x;  // 4194304
    const int m = idx >> 10, h = idx & 1023;
    const float* g = g_gates1 + (long)m * 4096;
    float gi = g[h], gf = g[h + 1024], gg = g[h + 2048], go = g[h + 3072];
    float c0n = g_c0all[idx];
    float c1 = sigf(gf) * c0n + sigf(gi) * tanhf(gg);
    float h1 = sigf(go) * tanhf(c1);
    const int b = m & 127, t = m >> 7;
    out[(long)(b * 32 + t) * 1024 + h] = h1;
}

// ---------------------------------------------------------------------------
// prep: tf32-rounded w0cat, w0e, w1c, embp (perm), plus biases
// ---------------------------------------------------------------------------
__global__ __launch_bounds__(256) void prep_kernel(
    const float* __restrict__ W_ih0, const float* __restrict__ W_hh0,
    const float* __restrict__ W_ih1, const float* __restrict__ W_hh1,
    const float* __restrict__ emb,
    const float* __restrict__ b_ih0, const float* __restrict__ b_hh0,
    const float* __restrict__ b_ih1, const float* __restrict__ b_hh1)
{
    const int i = blockIdx.x * 256 + threadIdx.x;
    const int stride = gridDim.x * 256;
    for (int idx = i; idx < 4096 * 2048; idx += stride) {
        const int n = idx >> 11, k = idx & 2047;
        g_w0cat[idx] = rnd_tf32((k < 1024) ? W_ih0[n * 2048 + 1024 + k]
                                           : W_hh0[n * 1024 + (k - 1024)]);
    }
    for (int idx = i; idx < 4096 * 1024; idx += stride) {
        const int n = idx >> 10, k = idx & 1023;
        g_w0e[idx] = rnd_tf32(W_ih0[n * 2048 + k]);
        g_w1c[idx] = rnd_tf32(W_ih1[idx] + W_hh1[idx]);
        const int m = idx >> 10;
        g_embp[idx] = rnd_tf32(emb[((m & 127) * 32 + (m >> 7)) * 1024 + k]);
    }
    if (i < 4096) {
        g_b0c[i] = b_ih0[i] + b_hh0[i];
        g_b1c[i] = b_ih1[i] + b_hh1[i];
    }
}

__global__ void transpose_round_kernel(const float* __restrict__ src, float* __restrict__ dst)
{
    __shared__ float tile[32][33];
    int x = blockIdx.x * 32 + threadIdx.x;
    int y = blockIdx.y * 32 + threadIdx.y;
    tile[threadIdx.y][threadIdx.x] = src[y * 1024 + x];
    __syncthreads();
    x = blockIdx.y * 32 + threadIdx.x;
    y = blockIdx.x * 32 + threadIdx.y;
    dst[y * 1024 + x] = rnd_tf32(tile[threadIdx.x][threadIdx.y]);
}

__global__ __launch_bounds__(256) void conv_feats_kernel(const float* __restrict__ feats)
{
    const long i = ((long)blockIdx.x * 256 + threadIdx.x) * 4;
    float4 f = *(const float4*)(feats + i);
    *(__nv_bfloat162*)&g_featsb[i] = __float22bfloat162_rn(make_float2(f.x, f.y));
    *(__nv_bfloat162*)&g_featsb[i + 2] = __float22bfloat162_rn(make_float2(f.z, f.w));
    float4 r;
    r.x = rnd_tf32(f.x); r.y = rnd_tf32(f.y); r.z = rnd_tf32(f.z); r.w = rnd_tf32(f.w);
    *(float4*)&g_featsr[i] = r;
}

// ---------------------------------------------------------------------------
extern "C" void kernel_launch(void* const* d_in, const int* in_sizes, int n_in,
                              void* d_out, int out_size)
{
    const float* feats = (const float*)d_in[0];
    const float* emb   = (const float*)d_in[1];
    const float* Wf    = (const float*)d_in[2];
    const float* Wh    = (const float*)d_in[3];
    const float* b_att = (const float*)d_in[4];
    const float* v     = (const float*)d_in[5];
    const float* W_ih0 = (const float*)d_in[6];
    const float* W_hh0 = (const float*)d_in[7];
    const float* b_ih0 = (const float*)d_in[8];
    const float* b_hh0 = (const float*)d_in[9];
    const float* W_ih1 = (const float*)d_in[10];
    const float* W_hh1 = (const float*)d_in[11];
    const float* b_ih1 = (const float*)d_in[12];
    const float* b_hh1 = (const float*)d_in[13];
    float* out = (float*)d_out;

    void *p_fprojb, *p_featsr, *p_embp, *p_pre0, *p_w0cat, *p_w0e, *p_w1c;
    void *p_wfT, *p_whT, *p_b0c, *p_b1c, *p_x, *p_c0, *p_qpart, *p_gpart;
    void *p_h0all, *p_gates1;
    cudaGetSymbolAddress(&p_fprojb, g_fprojb);
    cudaGetSymbolAddress(&p_featsr, g_featsr);
    cudaGetSymbolAddress(&p_embp, g_embp);
    cudaGetSymbolAddress(&p_pre0, g_pre0);
    cudaGetSymbolAddress(&p_w0cat, g_w0cat);
    cudaGetSymbolAddress(&p_w0e, g_w0e);
    cudaGetSymbolAddress(&p_w1c, g_w1c);
    cudaGetSymbolAddress(&p_wfT, g_wfT);
    cudaGetSymbolAddress(&p_whT, g_whT);
    cudaGetSymbolAddress(&p_b0c, g_b0c);
    cudaGetSymbolAddress(&p_b1c, g_b1c);
    cudaGetSymbolAddress(&p_x, g_x);
    cudaGetSymbolAddress(&p_c0, g_c0);
    cudaGetSymbolAddress(&p_qpart, g_qpart);
    cudaGetSymbolAddress(&p_gpart, g_gpart);
    cudaGetSymbolAddress(&p_h0all, g_h0all);
    cudaGetSymbolAddress(&p_gates1, g_gates1);

    constexpr int SMEM128 = (2 * 128 * 36 + 2 * 128 * 36) * 4;   // 73728
    constexpr int SMEM32  = (2 * 128 * 36 + 2 * 32 * 36) * 4;    // 46080
    cudaFuncSetAttribute(mma_gemm2<128, true, true, false>,
                         cudaFuncAttributeMaxDynamicSharedMemorySize, SMEM128);
    cudaFuncSetAttribute(mma_gemm2<128, true, false, false>,
                         cudaFuncAttributeMaxDynamicSharedMemorySize, SMEM128);

    prep_kernel<<<2048, 256>>>(W_ih0, W_hh0, W_ih1, W_hh1, emb,
                               b_ih0, b_hh0, b_ih1, b_hh1);
    transpose_round_kernel<<<dim3(32, 32), dim3(32, 32)>>>(Wf, (float*)p_wfT);
    transpose_round_kernel<<<dim3(32, 32), dim3(32, 32)>>>(Wh, (float*)p_whT);
    conv_feats_kernel<<<25088, 256>>>(feats);

    // f_proj(bf16) = featsr @ wfT^T + b_att
    mma_gemm2<128, true, true, false><<<dim3(196, 8, 1), 256, SMEM128>>>(
        (const float*)p_featsr, 1024, (const float*)p_wfT, 1024,
        p_fprojb, 1024, b_att, nullptr, 1024, 0);

    // pre0 = embp @ w0e^T + b0c
    mma_gemm2<128, true, false, false><<<dim3(32, 32, 1), 256, SMEM128>>>(
        (const float*)p_embp, 1024, (const float*)p_w0e, 1024,
        p_pre0, 4096, (const float*)p_b0c, nullptr, 1024, 0);

    cudaMemsetAsync(p_x, 0, 128 * 2048 * sizeof(float));
    cudaMemsetAsync(p_c0, 0, 128 * 1024 * sizeof(float));

    for (int t = 0; t < 32; t++) {
        // q partials: split-K=4
        mma_gemm2<32, false, false, false><<<dim3(1, 32, 4), 256, SMEM32>>>(
            (const float*)p_x + 1024, 2048, (const float*)p_whT, 1024,
            p_qpart, 1024, nullptr, nullptr, 256, 131072);

        attn_fused<<<128, 512>>>(v);

        // gates partials: split-K=2, pre0 slice added in z==0
        mma_gemm2<32, false, false, true><<<dim3(1, 128, 2), 256, SMEM32>>>(
            (const float*)p_x, 2048, (const float*)p_w0cat, 2048,
            p_gpart, 4096, nullptr,
            (const float*)p_pre0 + (size_t)t * 524288, 1024, 524288);

        cell0_kernel<<<512, 256>>>(t);
    }

    // layer 1 batched
    mma_gemm2<128, true, false, false><<<dim3(32, 32, 1), 256, SMEM128>>>(
        (const float*)p_h0all, 1024, (const float*)p_w1c, 1024,
        p_gates1, 4096, (const float*)p_b1c, nullptr, 1024, 0);

    cell1_kernel<<<16384, 256>>>(out);
}

// round 6
// speedup vs baseline: 2.8744x; 1.0783x over previous
#include <cuda_runtime.h>
#include <cuda_bf16.h>
#include <cstdint>

// ---------------------------------------------------------------------------
// B=128, T=32, N=196, E=FD=H=A=1024, 4H=4096, E+FD=2048
// ---------------------------------------------------------------------------

// ------------------------------ scratch ------------------------------------
__device__ __nv_bfloat16 g_fprojb[25088 * 1024];   // bf16 f_proj      51.4 MB
__device__ __nv_bfloat16 g_featsb[25088 * 1024];   // bf16 feats       51.4 MB
__device__ float g_featsr[25088 * 1024];           // tf32 feats      102.8 MB
__device__ float g_embp[4096 * 1024];              // perm+tf32 emb    16.8 MB
__device__ float g_pre0[32 * 128 * 4096];          // fp32             67.1 MB
__device__ float g_wqh[5120 * 1024];               // tf32 [Wh^T;Whh0] 21.0 MB
__device__ float g_w0a[4096 * 1024];               // tf32 Wih0 attn   16.8 MB
__device__ float g_w0e[4096 * 1024];               // tf32 Wih0 embed  16.8 MB
__device__ float g_w1c[4096 * 1024];               // tf32 Wih1+Whh1   16.8 MB
__device__ float g_wfT[1024 * 1024];               // tf32 Wf^T
__device__ float g_b0c[4096];
__device__ float g_b1c[4096];
__device__ float g_x[128 * 2048];                  // tf32 [attn | h0]
__device__ float g_c0[128 * 1024];
__device__ float g_q[128 * 1024];
__device__ float g_gpart[2 * 128 * 4096];          // gates halves
__device__ float g_h0all[32 * 128 * 1024];         // tf32 [t][b][h]
__device__ float g_c0all[32 * 128 * 1024];         // fp32
__device__ float g_gates1[32 * 128 * 4096];        // 67.1 MB

// ------------------------------ helpers ------------------------------------
__device__ __forceinline__ float fast_tanh(float x) {
    float r; asm("tanh.approx.f32 %0, %1;" : "=f"(r) : "f"(x)); return r;
}
__device__ __forceinline__ float sigf(float x) { return 1.f / (1.f + __expf(-x)); }
__device__ __forceinline__ float rnd_tf32(float x) {
    uint32_t r; asm("cvt.rna.tf32.f32 %0, %1;" : "=r"(r) : "f"(x));
    return __uint_as_float(r);
}
__device__ __forceinline__ void mma_tf32(float* c, const uint32_t* a, const uint32_t* b) {
    asm volatile(
        "mma.sync.aligned.m16n8k8.row.col.f32.tf32.tf32.f32 "
        "{%0,%1,%2,%3}, {%4,%5,%6,%7}, {%8,%9}, {%0,%1,%2,%3};"
        : "+f"(c[0]), "+f"(c[1]), "+f"(c[2]), "+f"(c[3])
        : "r"(a[0]), "r"(a[1]), "r"(a[2]), "r"(a[3]), "r"(b[0]), "r"(b[1]));
}
__device__ __forceinline__ uint32_t smem_u32(const void* p) {
    return (uint32_t)__cvta_generic_to_shared(p);
}
__device__ __forceinline__ void cp16(uint32_t dst, const void* src) {
    asm volatile("cp.async.cg.shared.global [%0], [%1], 16;" :: "r"(dst), "l"(src));
}
__device__ __forceinline__ void ldsm4(uint32_t* r, uint32_t addr) {
    asm volatile("ldmatrix.sync.aligned.m8n8.x4.shared.b16 {%0,%1,%2,%3}, [%4];"
        : "=r"(r[0]), "=r"(r[1]), "=r"(r[2]), "=r"(r[3]) : "r"(addr));
}

// ---------------------------------------------------------------------------
// tf32 MMA GEMM v3: C[M,N] = A[M,K] * B[N,K]^T, ldmatrix frags, multi-stage.
// BM=128. 256 threads, 8 warps 4x2 (WM=32, WN=BN/2). Operands pre-tf32.
//   QH: col<1024 -> g_q, else g_gpart (first half)
//   ADDPRE: += pre[row*ldc+col]
// ---------------------------------------------------------------------------
template <int BN, int STAGES, bool BIAS, bool OUTBF, bool ADDPRE, bool QH>
__global__ __launch_bounds__(256) void mma_gemm3(
    const float* __restrict__ A, int lda,
    const float* __restrict__ B, int ldb,
    void* __restrict__ Cv, int ldc,
    const float* __restrict__ bias,
    const float* __restrict__ pre,
    int K)
{
    constexpr int KC = 32;
    constexpr int PITCH = 36;
    constexpr int WN = BN / 2;
    constexpr int NFR = WN / 8;
    constexpr int ASZ = 128 * PITCH;
    constexpr int BSZ = BN * PITCH;
    constexpr int BCH = BN * 8 / 256;

    extern __shared__ float sm[];

    const int tid = threadIdx.x;
    const int wid = tid >> 5, lane = tid & 31;
    const int m0 = blockIdx.x * 128;
    const int n0 = blockIdx.y * BN;
    const int wm = (wid & 3) * 32;
    const int wn = (wid >> 2) * WN;
    const int g = lane >> 2, tg = lane & 3;
    const int NIT = K / KC;

    const int lrow = ((lane >> 3) & 1) * 8 + (lane & 7);  // A row-within-16
    const int lcolA = (lane >> 4) * 4;                    // A col 0/4
    const int browp = (lane >> 4) * 8 + (lane & 7);       // B row-within-16
    const int bcol = ((lane >> 3) & 1) * 4;               // B col 0/4

    float acc[2][NFR][4];
#pragma unroll
    for (int f = 0; f < 2; f++)
#pragma unroll
        for (int j = 0; j < NFR; j++)
#pragma unroll
            for (int k = 0; k < 4; k++) acc[f][j][k] = 0.f;

    auto issue = [&](int it) {
        const int s = it % STAGES;
        float* As = sm + s * (ASZ + BSZ);
        float* Bs = As + ASZ;
        const long kb = (long)it * KC;
#pragma unroll
        for (int i = 0; i < 4; i++) {
            int c = tid + i * 256;
            int row = c >> 3, kq = c & 7;
            cp16(smem_u32(As + row * PITCH + kq * 4),
                 A + (long)(m0 + row) * lda + kb + kq * 4);
        }
#pragma unroll
        for (int i = 0; i < BCH; i++) {
            int c = tid + i * 256;
            int row = c >> 3, kq = c & 7;
            cp16(smem_u32(Bs + row * PITCH + kq * 4),
                 B + (long)(n0 + row) * ldb + kb + kq * 4);
        }
        asm volatile("cp.async.commit_group;" ::: "memory");
    };

    issue(0);
    if (STAGES >= 3 && NIT > 1) issue(1);

    for (int it = 0; it < NIT; it++) {
        if (STAGES >= 3 && it + 1 < NIT)
            asm volatile("cp.async.wait_group 1;" ::: "memory");
        else
            asm volatile("cp.async.wait_group 0;" ::: "memory");
        __syncthreads();
        if (it + STAGES - 1 < NIT) issue(it + STAGES - 1);

        const int s = it % STAGES;
        const float* As = sm + s * (ASZ + BSZ);
        const float* Bs = As + ASZ;
        const uint32_t aBase = smem_u32(As);
        const uint32_t bBase = smem_u32(Bs);

#pragma unroll
        for (int ko = 0; ko < KC; ko += 8) {
            uint32_t af[2][4];
#pragma unroll
            for (int f = 0; f < 2; f++)
                ldsm4(af[f], aBase + ((wm + f * 16 + lrow) * PITCH + ko + lcolA) * 4);
            uint32_t bf[NFR][2];
#pragma unroll
            for (int nf = 0; nf < NFR; nf += 2) {
                uint32_t tmp[4];
                ldsm4(tmp, bBase + ((wn + nf * 8 + browp) * PITCH + ko + bcol) * 4);
                bf[nf][0] = tmp[0]; bf[nf][1] = tmp[1];
                bf[nf + 1][0] = tmp[2]; bf[nf + 1][1] = tmp[3];
            }
#pragma unroll
            for (int f = 0; f < 2; f++)
#pragma unroll
                for (int nf = 0; nf < NFR; nf++)
                    mma_tf32(acc[f][nf], af[f], bf[nf]);
        }
    }

#pragma unroll
    for (int f = 0; f < 2; f++) {
#pragma unroll
        for (int nf = 0; nf < NFR; nf++) {
            const int col = n0 + wn + nf * 8 + tg * 2;
#pragma unroll
            for (int h = 0; h < 2; h++) {
                const long row = m0 + wm + f * 16 + g + h * 8;
                float v0 = acc[f][nf][h * 2 + 0];
                float v1 = acc[f][nf][h * 2 + 1];
                if (BIAS) { v0 += bias[col]; v1 += bias[col + 1]; }
                if (ADDPRE) {
                    v0 += pre[row * ldc + col];
                    v1 += pre[row * ldc + col + 1];
                }
                if (QH) {
                    if (col < 1024) {
                        g_q[row * 1024 + col] = v0;
                        g_q[row * 1024 + col + 1] = v1;
                    } else {
                        g_gpart[row * 4096 + col - 1024] = v0;
                        g_gpart[row * 4096 + col - 1023] = v1;
                    }
                } else if (OUTBF) {
                    __nv_bfloat16* Cb = (__nv_bfloat16*)Cv;
                    *(__nv_bfloat162*)&Cb[row * ldc + col] =
                        __float22bfloat162_rn(make_float2(v0, v1));
                } else {
                    float* Cf = (float*)Cv;
                    Cf[row * ldc + col] = v0;
                    Cf[row * ldc + col + 1] = v1;
                }
            }
        }
    }
}

// ---------------------------------------------------------------------------
__global__ __launch_bounds__(512) void attn_fused(const float* __restrict__ v)
{
    const int b = blockIdx.x, tid = threadIdx.x;
    const int warp = tid >> 5, lane = tid & 31;
    __shared__ float qs[1024];
    __shared__ float sal[256];
    __shared__ float red[16];

    for (int a = tid; a < 1024; a += 512) qs[a] = g_q[b * 1024 + a];
    __syncthreads();

    for (int n = warp; n < 196; n += 16) {
        const __nv_bfloat16* fp = g_fprojb + (long)(b * 196 + n) * 1024;
        float acc = 0.f;
#pragma unroll
        for (int i = 0; i < 4; i++) {
            const int k0 = i * 256 + lane * 8;
            uint4 raw = *(const uint4*)(fp + k0);
            float2 f0 = __bfloat1622float2(*reinterpret_cast<__nv_bfloat162*>(&raw.x));
            float2 f1 = __bfloat1622float2(*reinterpret_cast<__nv_bfloat162*>(&raw.y));
            float2 f2 = __bfloat1622float2(*reinterpret_cast<__nv_bfloat162*>(&raw.z));
            float2 f3 = __bfloat1622float2(*reinterpret_cast<__nv_bfloat162*>(&raw.w));
            float4 q0 = *(const float4*)(qs + k0);
            float4 q1 = *(const float4*)(qs + k0 + 4);
            float4 v0 = *(const float4*)(v + k0);
            float4 v1 = *(const float4*)(v + k0 + 4);
            acc = fmaf(v0.x, fast_tanh(f0.x + q0.x), acc);
            acc = fmaf(v0.y, fast_tanh(f0.y + q0.y), acc);
            acc = fmaf(v0.z, fast_tanh(f1.x + q0.z), acc);
            acc = fmaf(v0.w, fast_tanh(f1.y + q0.w), acc);
            acc = fmaf(v1.x, fast_tanh(f2.x + q1.x), acc);
            acc = fmaf(v1.y, fast_tanh(f2.y + q1.y), acc);
            acc = fmaf(v1.z, fast_tanh(f3.x + q1.z), acc);
            acc = fmaf(v1.w, fast_tanh(f3.y + q1.w), acc);
        }
#pragma unroll
        for (int o = 16; o; o >>= 1) acc += __shfl_xor_sync(0xffffffffu, acc, o);
        if (lane == 0) sal[n] = acc;
    }
    __syncthreads();

    float s = (tid < 196) ? sal[tid] : -3.0e38f;
    float m = s;
#pragma unroll
    for (int o = 16; o; o >>= 1) m = fmaxf(m, __shfl_xor_sync(0xffffffffu, m, o));
    if (lane == 0) red[warp] = m;
    __syncthreads();
    if (tid == 0) {
        float t2 = red[0];
        for (int i = 1; i < 16; i++) t2 = fmaxf(t2, red[i]);
        red[0] = t2;
    }
    __syncthreads();
    const float M = red[0];
    __syncthreads();

    float e = (tid < 196) ? __expf(s - M) : 0.f;
    float sm2 = e;
#pragma unroll
    for (int o = 16; o; o >>= 1) sm2 += __shfl_xor_sync(0xffffffffu, sm2, o);
    if (lane == 0) red[warp] = sm2;
    __syncthreads();
    if (tid == 0) {
        float t2 = 0.f;
        for (int i = 0; i < 16; i++) t2 += red[i];
        red[0] = t2;
    }
    __syncthreads();
    const float S = red[0];
    __syncthreads();
    if (tid < 196) sal[tid] = e / S;
    __syncthreads();

    const __nv_bfloat16* fb = g_featsb + (long)b * 196 * 1024;
    float a0 = 0.f, a1 = 0.f;
#pragma unroll 4
    for (int n = 0; n < 196; n++) {
        float al = sal[n];
        float2 f = __bfloat1622float2(*(const __nv_bfloat162*)(fb + n * 1024 + tid * 2));
        a0 = fmaf(al, f.x, a0);
        a1 = fmaf(al, f.y, a1);
    }
    g_x[b * 2048 + tid * 2] = rnd_tf32(a0);
    g_x[b * 2048 + tid * 2 + 1] = rnd_tf32(a1);
}

// ---------------------------------------------------------------------------
__global__ __launch_bounds__(256) void cell0_kernel(int t)
{
    const int idx = blockIdx.x * 256 + threadIdx.x;  // 131072
    const int b = idx >> 10, h = idx & 1023;
    const float* g0 = g_gpart + b * 4096;
    const float* g1 = g_gpart + 524288 + b * 4096;
    float gi = g0[h] + g1[h];
    float gf = g0[h + 1024] + g1[h + 1024];
    float gg = g0[h + 2048] + g1[h + 2048];
    float go = g0[h + 3072] + g1[h + 3072];
    float c = g_c0[idx];
    float cn = sigf(gf) * c + sigf(gi) * tanhf(gg);
    float hn = sigf(go) * tanhf(cn);
    float hr = rnd_tf32(hn);
    g_c0[idx] = cn;
    g_x[b * 2048 + 1024 + h] = hr;
    g_c0all[t * 131072 + idx] = cn;
    g_h0all[t * 131072 + idx] = hr;
}

__global__ __launch_bounds__(256) void cell1_kernel(float* __restrict__ out)
{
    const int idx = blockIdx.x * 256 + threadIdx.x;  // 4194304
    const int m = idx >> 10, h = idx & 1023;
    const float* g = g_gates1 + (long)m * 4096;
    float gi = g[h], gf = g[h + 1024], gg = g[h + 2048], go = g[h + 3072];
    float c0n = g_c0all[idx];
    float c1 = sigf(gf) * c0n + sigf(gi) * tanhf(gg);
    float h1 = sigf(go) * tanhf(c1);
    const int b = m & 127, t = m >> 7;
    out[(long)(b * 32 + t) * 1024 + h] = h1;
}

// ---------------------------------------------------------------------------
__global__ __launch_bounds__(256) void prep_kernel(
    const float* __restrict__ W_ih0, const float* __restrict__ W_hh0,
    const float* __restrict__ W_ih1, const float* __restrict__ W_hh1,
    const float* __restrict__ emb,
    const float* __restrict__ b_ih0, const float* __restrict__ b_hh0,
    const float* __restrict__ b_ih1, const float* __restrict__ b_hh1)
{
    const int i = blockIdx.x * 256 + threadIdx.x;
    const int stride = gridDim.x * 256;
    for (int idx = i; idx < 4096 * 1024; idx += stride) {
        const int n = idx >> 10, k = idx & 1023;
        g_wqh[(1024 + n) * 1024 + k] = rnd_tf32(W_hh0[idx]);
        g_w0a[idx] = rnd_tf32(W_ih0[n * 2048 + 1024 + k]);
        g_w0e[idx] = rnd_tf32(W_ih0[n * 2048 + k]);
        g_w1c[idx] = rnd_tf32(W_ih1[idx] + W_hh1[idx]);
        const int m = idx >> 10;
        g_embp[idx] = rnd_tf32(emb[((m & 127) * 32 + (m >> 7)) * 1024 + k]);
    }
    if (i < 4096) {
        g_b0c[i] = b_ih0[i] + b_hh0[i];
        g_b1c[i] = b_ih1[i] + b_hh1[i];
    }
}

__global__ void transpose_round_kernel(const float* __restrict__ src, float* __restrict__ dst)
{
    __shared__ float tile[32][33];
    int x = blockIdx.x * 32 + threadIdx.x;
    int y = blockIdx.y * 32 + threadIdx.y;
    tile[threadIdx.y][threadIdx.x] = src[y * 1024 + x];
    __syncthreads();
    x = blockIdx.y * 32 + threadIdx.x;
    y = blockIdx.x * 32 + threadIdx.y;
    dst[y * 1024 + x] = rnd_tf32(tile[threadIdx.x][threadIdx.y]);
}

__global__ __launch_bounds__(256) void conv_feats_kernel(const float* __restrict__ feats)
{
    const long i = ((long)blockIdx.x * 256 + threadIdx.x) * 4;
    float4 f = *(const float4*)(feats + i);
    *(__nv_bfloat162*)&g_featsb[i] = __float22bfloat162_rn(make_float2(f.x, f.y));
    *(__nv_bfloat162*)&g_featsb[i + 2] = __float22bfloat162_rn(make_float2(f.z, f.w));
    float4 r;
    r.x = rnd_tf32(f.x); r.y = rnd_tf32(f.y); r.z = rnd_tf32(f.z); r.w = rnd_tf32(f.w);
    *(float4*)&g_featsr[i] = r;
}

// ---------------------------------------------------------------------------
extern "C" void kernel_launch(void* const* d_in, const int* in_sizes, int n_in,
                              void* d_out, int out_size)
{
    const float* feats = (const float*)d_in[0];
    const float* emb   = (const float*)d_in[1];
    const float* Wf    = (const float*)d_in[2];
    const float* Wh    = (const float*)d_in[3];
    const float* b_att = (const float*)d_in[4];
    const float* v     = (const float*)d_in[5];
    const float* W_ih0 = (const float*)d_in[6];
    const float* W_hh0 = (const float*)d_in[7];
    const float* b_ih0 = (const float*)d_in[8];
    const float* b_hh0 = (const float*)d_in[9];
    const float* W_ih1 = (const float*)d_in[10];
    const float* W_hh1 = (const float*)d_in[11];
    const float* b_ih1 = (const float*)d_in[12];
    const float* b_hh1 = (const float*)d_in[13];
    float* out = (float*)d_out;

    void *p_fprojb, *p_featsr, *p_embp, *p_pre0, *p_wqh, *p_w0a, *p_w0e, *p_w1c;
    void *p_wfT, *p_b0c, *p_b1c, *p_x, *p_c0, *p_gpart, *p_h0all, *p_gates1;
    cudaGetSymbolAddress(&p_fprojb, g_fprojb);
    cudaGetSymbolAddress(&p_featsr, g_featsr);
    cudaGetSymbolAddress(&p_embp, g_embp);
    cudaGetSymbolAddress(&p_pre0, g_pre0);
    cudaGetSymbolAddress(&p_wqh, g_wqh);
    cudaGetSymbolAddress(&p_w0a, g_w0a);
    cudaGetSymbolAddress(&p_w0e, g_w0e);
    cudaGetSymbolAddress(&p_w1c, g_w1c);
    cudaGetSymbolAddress(&p_wfT, g_wfT);
    cudaGetSymbolAddress(&p_b0c, g_b0c);
    cudaGetSymbolAddress(&p_b1c, g_b1c);
    cudaGetSymbolAddress(&p_x, g_x);
    cudaGetSymbolAddress(&p_c0, g_c0);
    cudaGetSymbolAddress(&p_gpart, g_gpart);
    cudaGetSymbolAddress(&p_h0all, g_h0all);
    cudaGetSymbolAddress(&p_gates1, g_gates1);

    constexpr int PITCH = 36;
    constexpr int SMEM128 = 2 * (128 * PITCH + 128 * PITCH) * 4;   // 73728
    constexpr int SMEM32  = 3 * (128 * PITCH + 32 * PITCH) * 4;    // 69120
    cudaFuncSetAttribute(mma_gemm3<128, 2, true, true, false, false>,
                         cudaFuncAttributeMaxDynamicSharedMemorySize, SMEM128);
    cudaFuncSetAttribute(mma_gemm3<128, 2, true, false, false, false>,
                         cudaFuncAttributeMaxDynamicSharedMemorySize, SMEM128);
    cudaFuncSetAttribute(mma_gemm3<32, 3, false, false, false, true>,
                         cudaFuncAttributeMaxDynamicSharedMemorySize, SMEM32);
    cudaFuncSetAttribute(mma_gemm3<32, 3, false, false, true, false>,
                         cudaFuncAttributeMaxDynamicSharedMemorySize, SMEM32);

    prep_kernel<<<2048, 256>>>(W_ih0, W_hh0, W_ih1, W_hh1, emb,
                               b_ih0, b_hh0, b_ih1, b_hh1);
    transpose_round_kernel<<<dim3(32, 32), dim3(32, 32)>>>(Wf, (float*)p_wfT);
    transpose_round_kernel<<<dim3(32, 32), dim3(32, 32)>>>(Wh, (float*)p_wqh);
    conv_feats_kernel<<<25088, 256>>>(feats);

    mma_gemm3<128, 2, true, true, false, false><<<dim3(196, 8), 256, SMEM128>>>(
        (const float*)p_featsr, 1024, (const float*)p_wfT, 1024,
        p_fprojb, 1024, b_att, nullptr, 1024);

    mma_gemm3<128, 2, true, false, false, false><<<dim3(32, 32), 256, SMEM128>>>(
        (const float*)p_embp, 1024, (const float*)p_w0e, 1024,
        p_pre0, 4096, (const float*)p_b0c, nullptr, 1024);

    cudaMemsetAsync(p_x, 0, 128 * 2048 * sizeof(float));
    cudaMemsetAsync(p_c0, 0, 128 * 1024 * sizeof(float));

    float* gpart1 = (float*)p_gpart + 524288;

    for (int t = 0; t < 32; t++) {
        // [q | gates_h] = h0 @ [Wh^T ; Whh0]^T
        mma_gemm3<32, 3, false, false, false, true><<<dim3(1, 160), 256, SMEM32>>>(
            (const float*)p_x + 1024, 2048, (const float*)p_wqh, 1024,
            nullptr, 0, nullptr, nullptr, 1024);

        attn_fused<<<128, 512>>>(v);

        // gates_a = attn @ w0a^T + pre0_t  -> gpart[1]
        mma_gemm3<32, 3, false, false, true, false><<<dim3(1, 128), 256, SMEM32>>>(
            (const float*)p_x, 2048, (const float*)p_w0a, 1024,
            gpart1, 4096, nullptr,
            (const float*)p_pre0 + (size_t)t * 524288, 1024);

        cell0_kernel<<<512, 256>>>(t);
    }

    mma_gemm3<128, 2, true, false, false, false><<<dim3(32, 32), 256, SMEM128>>>(
        (const float*)p_h0all, 1024, (const float*)p_w1c, 1024,
        p_gates1, 4096, (const float*)p_b1c, nullptr, 1024);

    cell1_kernel<<<16384, 256>>>(out);
}